// round 1
// baseline (speedup 1.0000x reference)
#include <cuda_runtime.h>
#include <math.h>

// Problem geometry: x shape (2,1,160,160,16), q/lambda shape (2,3,160,160,16), f32, C-order.
#define PP 2
#define XD 160
#define YD 160
#define TD 16
#define LPB (XD*YD)          // lines per batch-channel = 25600
#define NLINES (PP*LPB)      // x-shaped lines = 51200
#define NV (NLINES*4)        // float4 elements in an x-shaped array = 204800
#define NQV (3*NV)           // float4 elements in q/lambda = 614400
#define T_ITERS 48

// Persistent state (static device memory; no allocation in kernel_launch).
__device__ float4 g_p4[NV];
__device__ float4 g_q4[NQV];
__device__ float4 g_xbar4[NV];

__device__ __forceinline__ float shfl_quad(float v, int lane, int delta4) {
    // shuffle within the 4-lane group that owns one T-line (T=16 = 4 float4)
    int src = (lane & ~3) | ((lane + delta4) & 3);
    return __shfl_sync(0xffffffffu, v, src);
}

__device__ __forceinline__ float4 f4sub(float4 a, float4 b) {
    return make_float4(a.x-b.x, a.y-b.y, a.z-b.z, a.w-b.w);
}

// ---------------------------------------------------------------------------
// Init: p = x, xbar = x, x0(=d_out) = x, q = 0
// ---------------------------------------------------------------------------
__global__ void kinit(const float4* __restrict__ x, float4* __restrict__ x0out) {
    int gid = blockIdx.x * blockDim.x + threadIdx.x;
    if (gid < NQV) g_q4[gid] = make_float4(0.f, 0.f, 0.f, 0.f);
    if (gid < NV) {
        float4 v = x[gid];
        g_p4[gid] = v;
        g_xbar4[gid] = v;
        x0out[gid] = v;
    }
}

// ---------------------------------------------------------------------------
// K1: p' = (p + sigma*(xbar - xnoisy)) / (1+sigma)
//     q' = clip(q + sigma * grad3(xbar), -lambda, +lambda)
// grad3[d](i) = xbar(i + e_d) - xbar(i), circular.
// ---------------------------------------------------------------------------
__global__ void __launch_bounds__(256) k1_pq(
    const float4* __restrict__ xn, const float4* __restrict__ lam,
    float sigma, float inv1ps)
{
    int gid = blockIdx.x * blockDim.x + threadIdx.x;   // [0, NV)
    int quad = gid & 3;
    int line = gid >> 2;
    int yi   = line % YD;
    int rem  = line / YD;
    int xi   = rem % XD;
    int pp   = rem / XD;
    int lane = threadIdx.x & 31;

    float4 xb = g_xbar4[gid];

    int dxp = (xi == XD-1) ? -(XD-1)*YD : YD;   // +1 along X (circular), in lines
    int dyp = (yi == YD-1) ? -(YD-1)   : 1;     // +1 along Y (circular), in lines
    float4 xbxp = g_xbar4[(line + dxp)*4 + quad];
    float4 xbyp = g_xbar4[(line + dyp)*4 + quad];

    // p update (pointwise)
    {
        float4 xnv = xn[gid];
        float4 pv  = g_p4[gid];
        pv.x = (pv.x + sigma*(xb.x - xnv.x)) * inv1ps;
        pv.y = (pv.y + sigma*(xb.y - xnv.y)) * inv1ps;
        pv.z = (pv.z + sigma*(xb.z - xnv.z)) * inv1ps;
        pv.w = (pv.w + sigma*(xb.w - xnv.w)) * inv1ps;
        g_p4[gid] = pv;
    }

    // t-roll (+1) of xbar within the 16-long T line via lane shuffle
    float nxt = shfl_quad(xb.x, lane, 1);
    float4 gt = make_float4(xb.y - xb.x, xb.z - xb.y, xb.w - xb.z, nxt - xb.w);
    float4 gx = f4sub(xbxp, xb);
    float4 gy = f4sub(xbyp, xb);

    int qline0 = pp*3*LPB + xi*YD + yi;   // d=0 line; d advances by LPB

    #pragma unroll
    for (int d = 0; d < 3; d++) {
        int qi = (qline0 + d*LPB)*4 + quad;
        float4 g = (d == 0) ? gx : (d == 1) ? gy : gt;
        float4 qv = g_q4[qi];
        float4 lv = lam[qi];
        qv.x = fminf(fmaxf(qv.x + sigma*g.x, -lv.x), lv.x);
        qv.y = fminf(fmaxf(qv.y + sigma*g.y, -lv.y), lv.y);
        qv.z = fminf(fmaxf(qv.z + sigma*g.z, -lv.z), lv.z);
        qv.w = fminf(fmaxf(qv.w + sigma*g.w, -lv.w), lv.w);
        g_q4[qi] = qv;
    }
}

// ---------------------------------------------------------------------------
// K2: adj(i)  = sum_d q_d(i - e_d) - q_d(i)      (circular)
//     x1      = x0 - tau*p - tau*adj
//     xbar    = (1+theta)*x1 - theta*x0
//     x0 <- x1 (x0 lives in d_out)
// ---------------------------------------------------------------------------
__global__ void __launch_bounds__(256) k2_x(
    float4* __restrict__ x0out, float tau, float theta)
{
    int gid = blockIdx.x * blockDim.x + threadIdx.x;   // [0, NV)
    int quad = gid & 3;
    int line = gid >> 2;
    int yi   = line % YD;
    int rem  = line / YD;
    int xi   = rem % XD;
    int pp   = rem / XD;
    int lane = threadIdx.x & 31;

    int dxm = (xi == 0) ? (XD-1)*YD : -YD;   // -1 along X (circular), in lines
    int dym = (yi == 0) ? (YD-1)   : -1;     // -1 along Y (circular), in lines

    int qline0 = pp*3*LPB + xi*YD + yi;

    float4 q0  = g_q4[(qline0)*4 + quad];
    float4 q0m = g_q4[(qline0 + dxm)*4 + quad];
    float4 q1  = g_q4[(qline0 + LPB)*4 + quad];
    float4 q1m = g_q4[(qline0 + LPB + dym)*4 + quad];
    float4 q2  = g_q4[(qline0 + 2*LPB)*4 + quad];

    // t-roll (-1) of q2: element t gets q2[t-1]
    float prevw = shfl_quad(q2.w, lane, -1);
    float4 q2m = make_float4(prevw, q2.x, q2.y, q2.z);

    float4 adj;
    adj.x = (q0m.x - q0.x) + (q1m.x - q1.x) + (q2m.x - q2.x);
    adj.y = (q0m.y - q0.y) + (q1m.y - q1.y) + (q2m.y - q2.y);
    adj.z = (q0m.z - q0.z) + (q1m.z - q1.z) + (q2m.z - q2.z);
    adj.w = (q0m.w - q0.w) + (q1m.w - q1.w) + (q2m.w - q2.w);

    float4 pv  = g_p4[gid];
    float4 x0v = x0out[gid];

    float4 x1, xb;
    x1.x = x0v.x - tau*(pv.x + adj.x);
    x1.y = x0v.y - tau*(pv.y + adj.y);
    x1.z = x0v.z - tau*(pv.z + adj.z);
    x1.w = x0v.w - tau*(pv.w + adj.w);

    float opt = 1.0f + theta;
    xb.x = opt*x1.x - theta*x0v.x;
    xb.y = opt*x1.y - theta*x0v.y;
    xb.z = opt*x1.z - theta*x0v.z;
    xb.w = opt*x1.w - theta*x0v.w;

    x0out[gid]   = x1;
    g_xbar4[gid] = xb;
}

extern "C" void kernel_launch(void* const* d_in, const int* in_sizes, int n_in,
                              void* d_out, int out_size) {
    const float4* x   = (const float4*)d_in[0];   // (2,1,160,160,16) f32
    const float4* lam = (const float4*)d_in[1];   // (2,3,160,160,16) f32
    float4* out = (float4*)d_out;                 // (2,1,160,160,16) f32

    // Constants in f32, matching the reference's float32 math.
    float L     = sqrtf(13.0f);
    float s10   = 1.0f / (1.0f + expf(-10.0f));
    float sigma = s10 / L;
    float tau   = s10 / L;
    float theta = s10;
    float inv1ps = 1.0f / (1.0f + sigma);

    kinit<<<(NQV + 255)/256, 256>>>(x, out);
    for (int it = 0; it < T_ITERS; it++) {
        k1_pq<<<NV/256, 256>>>(x, lam, sigma, inv1ps);
        k2_x <<<NV/256, 256>>>(out, tau, theta);
    }
}

// round 2
// speedup vs baseline: 1.2617x; 1.2617x over previous
#include <cuda_runtime.h>
#include <math.h>

// Geometry: x (2,1,160,160,16), q/lambda (2,3,160,160,16), f32, C-order.
#define PP 2
#define XD 160
#define YD 160
#define LPB (XD*YD)          // lines per batch = 25600 (line = 16 t-floats = 4 float4)
#define NV (PP*LPB*4)        // float4 count in x-shaped array = 204800
#define NQV (3*NV)           // float4 count in q/lambda = 614400
#define T_ITERS 48
#define TX 8
#define TY 8

// Double-buffered state (neighbor reads race with writes otherwise).
__device__ float4 g_p4[NV];
__device__ float4 g_q4[2][NQV];
__device__ float4 g_xb4[2][NV];

__device__ __forceinline__ float shfl_quad(float v, int lane, int delta4) {
    int src = (lane & ~3) | ((lane + delta4) & 3);
    return __shfl_sync(0xffffffffu, v, src);
}
__device__ __forceinline__ float4 f4sub(float4 a, float4 b) {
    return make_float4(a.x-b.x, a.y-b.y, a.z-b.z, a.w-b.w);
}
__device__ __forceinline__ float4 clip4(float4 q, float4 g, float s, float4 l) {
    float4 r;
    r.x = fminf(fmaxf(fmaf(s, g.x, q.x), -l.x), l.x);
    r.y = fminf(fmaxf(fmaf(s, g.y, q.y), -l.y), l.y);
    r.z = fminf(fmaxf(fmaf(s, g.z, q.z), -l.z), l.z);
    r.w = fminf(fmaxf(fmaf(s, g.w, q.w), -l.w), l.w);
    return r;
}

// ---------------------------------------------------------------------------
// Init: p = x, xbar[0] = x, x0(=d_out) = x, q[0] = 0
// ---------------------------------------------------------------------------
__global__ void kinit(const float4* __restrict__ x, float4* __restrict__ x0out) {
    int gid = blockIdx.x * blockDim.x + threadIdx.x;
    if (gid < NQV) g_q4[0][gid] = make_float4(0.f, 0.f, 0.f, 0.f);
    if (gid < NV) {
        float4 v = x[gid];
        g_p4[gid]    = v;
        g_xb4[0][gid] = v;
        x0out[gid]   = v;
    }
}

// ---------------------------------------------------------------------------
// Fused iteration:
//   p' = (p + s*(xbar - xn))/(1+s)
//   q'_d = clip(q_d + s*grad_d(xbar), +/-lambda)     [+halo q0 row, q1 col]
//   adj  = sum_d q'_d(i - e_d) - q'_d(i)             [q' from smem/regs]
//   x1   = x0 - tau*(p' + adj);  xbar' = (1+th)*x1 - th*x0
// ---------------------------------------------------------------------------
__global__ void __launch_bounds__(256) kstep(
    const float4* __restrict__ xn, const float4* __restrict__ lam,
    float4* __restrict__ x0out, int parity,
    float sigma, float inv1ps, float tau, float theta)
{
    const float4* __restrict__ qin  = g_q4[parity];
    float4*       __restrict__ qout = g_q4[parity ^ 1];
    const float4* __restrict__ xbin = g_xb4[parity];
    float4*       __restrict__ xbout= g_xb4[parity ^ 1];

    __shared__ float4 sq0[TX+1][TY][4];   // q0': [lx+1], halo row at [0]
    __shared__ float4 sq1[TX][TY+1][4];   // q1': [ly+1], halo col at [0]

    int bid = blockIdx.x;                 // 800 blocks: 2 batches x 20 x 20 tiles
    int pp  = bid / 400;
    int t   = bid % 400;
    int bx  = t / 20, by = t % 20;
    int x0g = bx * TX, y0g = by * TY;

    int tid  = threadIdx.x;
    int quad = tid & 3;
    int ll   = tid >> 2;                  // 0..63
    int lx   = ll >> 3;                   // 0..7
    int ly   = ll & 7;
    int lane = tid & 31;

    int base = pp * LPB;
    int gx = x0g + lx, gy = y0g + ly;
    int gid = (base + gx*YD + gy)*4 + quad;

    int gxp = (gx == XD-1) ? 0 : gx + 1;
    int gyp = (gy == YD-1) ? 0 : gy + 1;

    float4 xb  = xbin[gid];
    float4 xbx = xbin[(base + gxp*YD + gy )*4 + quad];
    float4 xby = xbin[(base + gx *YD + gyp)*4 + quad];

    // gradients (t-roll within 16-long line via 4-lane shuffle)
    float nxt = shfl_quad(xb.x, lane, 1);
    float4 gt  = make_float4(xb.y-xb.x, xb.z-xb.y, xb.w-xb.z, nxt-xb.w);
    float4 gxv = f4sub(xbx, xb);
    float4 gyv = f4sub(xby, xb);

    int qbase = pp * 3 * LPB;
    int ql0   = qbase + gx*YD + gy;

    float4 q0, q1, q2;
    { int qi = ql0*4 + quad;           q0 = clip4(qin[qi], gxv, sigma, lam[qi]); qout[qi] = q0; }
    { int qi = (ql0 + LPB)*4 + quad;   q1 = clip4(qin[qi], gyv, sigma, lam[qi]); qout[qi] = q1; }
    { int qi = (ql0 + 2*LPB)*4 + quad; q2 = clip4(qin[qi], gt,  sigma, lam[qi]); qout[qi] = q2; }

    sq0[lx+1][ly][quad] = q0;
    sq1[lx][ly+1][quad] = q1;

    // Halo q (owned & also written by the neighbor block; values identical).
    if (tid < 32) {               // q0 at (x0g-1, y0g+h)
        int h  = tid >> 2, hq = tid & 3;
        int hx = (x0g == 0) ? XD-1 : x0g - 1;
        int hy = y0g + h;
        float4 a = xbin[(base + hx *YD + hy)*4 + hq];
        float4 b = xbin[(base + x0g*YD + hy)*4 + hq];
        int qi = (qbase + hx*YD + hy)*4 + hq;
        sq0[0][h][hq] = clip4(qin[qi], f4sub(b, a), sigma, lam[qi]);
    } else if (tid < 64) {        // q1 at (x0g+h, y0g-1)
        int h  = (tid - 32) >> 2, hq = tid & 3;
        int hx = x0g + h;
        int hy = (y0g == 0) ? YD-1 : y0g - 1;
        float4 a = xbin[(base + hx*YD + hy )*4 + hq];
        float4 b = xbin[(base + hx*YD + y0g)*4 + hq];
        int qi = (qbase + LPB + hx*YD + hy)*4 + hq;
        sq1[h][0][hq] = clip4(qin[qi], f4sub(b, a), sigma, lam[qi]);
    }

    // p update (pointwise)
    float4 pv  = g_p4[gid];
    float4 xnv = xn[gid];
    pv.x = (pv.x + sigma*(xb.x - xnv.x)) * inv1ps;
    pv.y = (pv.y + sigma*(xb.y - xnv.y)) * inv1ps;
    pv.z = (pv.z + sigma*(xb.z - xnv.z)) * inv1ps;
    pv.w = (pv.w + sigma*(xb.w - xnv.w)) * inv1ps;
    g_p4[gid] = pv;

    __syncthreads();

    float4 q0m = sq0[lx][ly][quad];
    float4 q1m = sq1[lx][ly][quad];
    float prevw = shfl_quad(q2.w, lane, -1);
    float4 q2m = make_float4(prevw, q2.x, q2.y, q2.z);

    float4 adj;
    adj.x = (q0m.x - q0.x) + (q1m.x - q1.x) + (q2m.x - q2.x);
    adj.y = (q0m.y - q0.y) + (q1m.y - q1.y) + (q2m.y - q2.y);
    adj.z = (q0m.z - q0.z) + (q1m.z - q1.z) + (q2m.z - q2.z);
    adj.w = (q0m.w - q0.w) + (q1m.w - q1.w) + (q2m.w - q2.w);

    float4 x0v = x0out[gid];
    float4 x1, xbn;
    x1.x = x0v.x - tau*(pv.x + adj.x);
    x1.y = x0v.y - tau*(pv.y + adj.y);
    x1.z = x0v.z - tau*(pv.z + adj.z);
    x1.w = x0v.w - tau*(pv.w + adj.w);

    float opt = 1.0f + theta;
    xbn.x = opt*x1.x - theta*x0v.x;
    xbn.y = opt*x1.y - theta*x0v.y;
    xbn.z = opt*x1.z - theta*x0v.z;
    xbn.w = opt*x1.w - theta*x0v.w;

    x0out[gid] = x1;
    xbout[gid] = xbn;
}

extern "C" void kernel_launch(void* const* d_in, const int* in_sizes, int n_in,
                              void* d_out, int out_size) {
    const float4* x   = (const float4*)d_in[0];
    const float4* lam = (const float4*)d_in[1];
    float4* out = (float4*)d_out;

    float L     = sqrtf(13.0f);
    float s10   = 1.0f / (1.0f + expf(-10.0f));
    float sigma = s10 / L;
    float tau   = s10 / L;
    float theta = s10;
    float inv1ps = 1.0f / (1.0f + sigma);

    kinit<<<(NQV + 255)/256, 256>>>(x, out);
    for (int it = 0; it < T_ITERS; it++) {
        kstep<<<PP*400, 256>>>(x, lam, out, it & 1, sigma, inv1ps, tau, theta);
    }
}

// round 4
// speedup vs baseline: 1.4500x; 1.1492x over previous
#include <cuda_runtime.h>
#include <math.h>

// Geometry: x (2,1,160,160,16), q/lambda (2,3,160,160,16), f32, C-order.
#define PP 2
#define XD 160
#define YD 160
#define LPB (XD*YD)          // lines per batch = 25600 (line = 16 t-floats = 4 float4)
#define NV (PP*LPB*4)        // float4 count in x-shaped array = 204800
#define NQV (3*NV)           // float4/short4 count in q/lambda = 614400
#define T_ITERS 48
#define TX 8
#define TY 8
#define QS 32767.0f

// State. q double-buffered as int16 fixed-point (Q = q*32767), lambda as int16.
// p, x0(=d_out), xbar stay fp32 (bias-sensitive accumulators).
__device__ float4 g_p4[NV];
__device__ short4 g_qs[2][NQV];
__device__ short4 g_ls[NQV];
__device__ float4 g_xb4[2][NV];

__device__ __forceinline__ float shfl_quad(float v, int lane, int delta4) {
    int src = (lane & ~3) | ((lane + delta4) & 3);
    return __shfl_sync(0xffffffffu, v, src);
}
__device__ __forceinline__ float4 f4sub(float4 a, float4 b) {
    return make_float4(a.x-b.x, a.y-b.y, a.z-b.z, a.w-b.w);
}
// Q' = clamp(round(Q + sigma_s*g), -L, L) in int units; returns float of ints,
// writes packed short4. Identical arithmetic on main & halo paths -> bitwise
// deterministic across blocks.
__device__ __forceinline__ float4 qstep(short4 q, float4 g, float sigma_s,
                                        short4 l, short4* outp) {
    int ix = __float2int_rn(fmaf(sigma_s, g.x, (float)q.x));
    int iy = __float2int_rn(fmaf(sigma_s, g.y, (float)q.y));
    int iz = __float2int_rn(fmaf(sigma_s, g.z, (float)q.z));
    int iw = __float2int_rn(fmaf(sigma_s, g.w, (float)q.w));
    ix = max(-(int)l.x, min(ix, (int)l.x));
    iy = max(-(int)l.y, min(iy, (int)l.y));
    iz = max(-(int)l.z, min(iz, (int)l.z));
    iw = max(-(int)l.w, min(iw, (int)l.w));
    *outp = make_short4((short)ix, (short)iy, (short)iz, (short)iw);
    return make_float4((float)ix, (float)iy, (float)iz, (float)iw);
}

// ---------------------------------------------------------------------------
// Init: p = x, xbar[0] = x, x0(=d_out) = x, q[0] = 0, g_ls = round(lam*32767)
// ---------------------------------------------------------------------------
__global__ void kinit(const float4* __restrict__ x, const float4* __restrict__ lam,
                      float4* __restrict__ x0out) {
    int gid = blockIdx.x * blockDim.x + threadIdx.x;
    if (gid < NQV) {
        g_qs[0][gid] = make_short4(0, 0, 0, 0);
        float4 l = lam[gid];
        g_ls[gid] = make_short4((short)__float2int_rn(l.x * QS),
                                (short)__float2int_rn(l.y * QS),
                                (short)__float2int_rn(l.z * QS),
                                (short)__float2int_rn(l.w * QS));
    }
    if (gid < NV) {
        float4 v = x[gid];
        g_p4[gid]     = v;
        g_xb4[0][gid] = v;
        x0out[gid]    = v;
    }
}

// ---------------------------------------------------------------------------
// Fused iteration (q/lambda int16 fixed-point, all math fp32):
//   p' = (p + s*(xbar - xn))/(1+s)
//   Q'_d = clamp(round(Q_d + s*32767*grad_d(xbar)), +/-Lam)   [+halo row/col]
//   adj  = (sum_d Q'_d(i-e_d) - Q'_d(i)) / 32767
//   x1   = x0 - tau*(p' + adj);  xbar' = (1+th)*x1 - th*x0
// ---------------------------------------------------------------------------
__global__ void __launch_bounds__(256) kstep(
    const float4* __restrict__ xn, float4* __restrict__ x0out, int parity,
    float sigma, float sigma_s, float inv1ps, float tau, float tau_s, float theta)
{
    const short4* __restrict__ qin   = g_qs[parity];
    short4*       __restrict__ qout  = g_qs[parity ^ 1];
    const float4* __restrict__ xbin  = g_xb4[parity];
    float4*       __restrict__ xbout = g_xb4[parity ^ 1];
    const short4* __restrict__ ls    = g_ls;

    __shared__ float4 sq0[TX+1][TY][4];   // Q0': [lx+1], halo row at [0]  (int units)
    __shared__ float4 sq1[TX][TY+1][4];   // Q1': [ly+1], halo col at [0]

    int bid = blockIdx.x;                 // 800 blocks: 2 batches x 20 x 20 tiles
    int pp  = bid / 400;
    int t   = bid % 400;
    int bx  = t / 20, by = t % 20;
    int x0g = bx * TX, y0g = by * TY;

    int tid  = threadIdx.x;
    int quad = tid & 3;
    int ll   = tid >> 2;                  // 0..63
    int lx   = ll >> 3;                   // 0..7
    int ly   = ll & 7;
    int lane = tid & 31;

    int base = pp * LPB;
    int gx = x0g + lx, gy = y0g + ly;
    int gid = (base + gx*YD + gy)*4 + quad;

    int gxp = (gx == XD-1) ? 0 : gx + 1;
    int gyp = (gy == YD-1) ? 0 : gy + 1;

    float4 xb  = xbin[gid];
    float4 xbx = xbin[(base + gxp*YD + gy )*4 + quad];
    float4 xby = xbin[(base + gx *YD + gyp)*4 + quad];

    // gradients (t-roll within 16-long line via 4-lane shuffle)
    float nxt = shfl_quad(xb.x, lane, 1);
    float4 gt  = make_float4(xb.y-xb.x, xb.z-xb.y, xb.w-xb.z, nxt-xb.w);
    float4 gxv = f4sub(xbx, xb);
    float4 gyv = f4sub(xby, xb);

    int qbase = pp * 3 * LPB;
    int ql0   = qbase + gx*YD + gy;

    float4 Q0, Q1, Q2;
    { int qi = ql0*4 + quad;           Q0 = qstep(qin[qi], gxv, sigma_s, ls[qi], &qout[qi]); }
    { int qi = (ql0 + LPB)*4 + quad;   Q1 = qstep(qin[qi], gyv, sigma_s, ls[qi], &qout[qi]); }
    { int qi = (ql0 + 2*LPB)*4 + quad; Q2 = qstep(qin[qi], gt,  sigma_s, ls[qi], &qout[qi]); }

    sq0[lx+1][ly][quad] = Q0;
    sq1[lx][ly+1][quad] = Q1;

    // Halo q (also computed by the neighbor block; identical arithmetic).
    if (tid < 32) {               // Q0 at (x0g-1, y0g+h)
        int h  = tid >> 2, hq = tid & 3;
        int hx = (x0g == 0) ? XD-1 : x0g - 1;
        int hy = y0g + h;
        float4 a = xbin[(base + hx *YD + hy)*4 + hq];
        float4 b = xbin[(base + x0g*YD + hy)*4 + hq];
        int qi = (qbase + hx*YD + hy)*4 + hq;
        short4 dummy;
        sq0[0][h][hq] = qstep(qin[qi], f4sub(b, a), sigma_s, ls[qi], &dummy);
    } else if (tid < 64) {        // Q1 at (x0g+h, y0g-1)
        int h  = (tid - 32) >> 2, hq = tid & 3;
        int hx = x0g + h;
        int hy = (y0g == 0) ? YD-1 : y0g - 1;
        float4 a = xbin[(base + hx*YD + hy )*4 + hq];
        float4 b = xbin[(base + hx*YD + y0g)*4 + hq];
        int qi = (qbase + LPB + hx*YD + hy)*4 + hq;
        short4 dummy;
        sq1[h][0][hq] = qstep(qin[qi], f4sub(b, a), sigma_s, ls[qi], &dummy);
    }

    // p update (pointwise, fp32)
    float4 pv  = g_p4[gid];
    float4 xnv = xn[gid];
    pv.x = (pv.x + sigma*(xb.x - xnv.x)) * inv1ps;
    pv.y = (pv.y + sigma*(xb.y - xnv.y)) * inv1ps;
    pv.z = (pv.z + sigma*(xb.z - xnv.z)) * inv1ps;
    pv.w = (pv.w + sigma*(xb.w - xnv.w)) * inv1ps;
    g_p4[gid] = pv;

    __syncthreads();

    float4 Q0m = sq0[lx][ly][quad];
    float4 Q1m = sq1[lx][ly][quad];
    float prevw = shfl_quad(Q2.w, lane, -1);
    float4 Q2m = make_float4(prevw, Q2.x, Q2.y, Q2.z);

    float4 adjQ;   // divergence in int units
    adjQ.x = (Q0m.x - Q0.x) + (Q1m.x - Q1.x) + (Q2m.x - Q2.x);
    adjQ.y = (Q0m.y - Q0.y) + (Q1m.y - Q1.y) + (Q2m.y - Q2.y);
    adjQ.z = (Q0m.z - Q0.z) + (Q1m.z - Q1.z) + (Q2m.z - Q2.z);
    adjQ.w = (Q0m.w - Q0.w) + (Q1m.w - Q1.w) + (Q2m.w - Q2.w);

    float4 x0v = x0out[gid];
    float4 x1, xbn;
    x1.x = x0v.x - tau*pv.x - tau_s*adjQ.x;
    x1.y = x0v.y - tau*pv.y - tau_s*adjQ.y;
    x1.z = x0v.z - tau*pv.z - tau_s*adjQ.z;
    x1.w = x0v.w - tau*pv.w - tau_s*adjQ.w;

    float opt = 1.0f + theta;
    xbn.x = opt*x1.x - theta*x0v.x;
    xbn.y = opt*x1.y - theta*x0v.y;
    xbn.z = opt*x1.z - theta*x0v.z;
    xbn.w = opt*x1.w - theta*x0v.w;

    x0out[gid] = x1;
    xbout[gid] = xbn;
}

extern "C" void kernel_launch(void* const* d_in, const int* in_sizes, int n_in,
                              void* d_out, int out_size) {
    const float4* x   = (const float4*)d_in[0];
    const float4* lam = (const float4*)d_in[1];
    float4* out = (float4*)d_out;

    float L     = sqrtf(13.0f);
    float s10   = 1.0f / (1.0f + expf(-10.0f));
    float sigma = s10 / L;
    float tau   = s10 / L;
    float theta = s10;
    float inv1ps = 1.0f / (1.0f + sigma);
    float sigma_s = sigma * QS;
    float tau_s   = tau / QS;

    kinit<<<(NQV + 255)/256, 256>>>(x, lam, out);
    for (int it = 0; it < T_ITERS; it++) {
        kstep<<<PP*400, 256>>>(x, out, it & 1, sigma, sigma_s, inv1ps,
                               tau, tau_s, theta);
    }
}